// round 15
// baseline (speedup 1.0000x reference)
#include <cuda_runtime.h>
#include <cooperative_groups.h>
namespace cg = cooperative_groups;

#define VN   64
#define BN   200
#define NSW  10
#define ECNT 63
#define MN   73
#define FIN  32
#define HID  64
#define MAXE 146
#define NT   512
#define NWARP (NT / 32)
#define WPAD 68
#define OUTW (MN + VN + MN)   // 210
#define HEDG 73               // edges per rank (off(32) == 73)
#define HNOD 32               // nodes per rank

// ---------------- shared memory layout (floats) ----------------------------
constexpr int O_S    = 0;
constexpr int O_X    = O_S  + MAXE * HID;       // 9344
constexpr int O_B0   = O_X  + VN * HID;         // 13440
constexpr int O_B1   = O_B0 + VN * HID;         // 17536
constexpr int O_W    = O_B1 + VN * HID;         // 21632  (transposed, 64*WPAD)
constexpr int O_XG   = O_W  + HID * WPAD;       // 25984
constexpr int O_EMB  = O_XG + HID;              // 26048
constexpr int O_SW   = O_EMB + 2 * FIN;         // 26112
constexpr int O_G    = O_SW + NSW * HID;        // 26752
constexpr int O_OUTS = O_G + 192;               // 26944
constexpr int O_OUTC = O_OUTS + 40;             // 26984
constexpr int O_VP   = O_OUTC + 192;            // 27176
constexpr int O_VC   = O_VP + 80;               // 27256
constexpr int O_DI   = O_VC + 80;               // 27336
constexpr int O_FEND = O_DI + VN;               // 27400 floats

constexpr int I_EV   = 0;
constexpr int I_EW   = I_EV + MAXE;
constexpr int I_EFL  = I_EW + MAXE;
constexpr int I_OFF  = I_EFL + MAXE;
constexpr int I_AI   = I_OFF + VN + 1 + 2;
constexpr int I_AJ   = I_AI + 64;
constexpr int I_SI   = I_AJ + 64;
constexpr int I_SJ   = I_SI + 16;
constexpr int I_SLOT = I_SJ + 16;
constexpr int I_END  = I_SLOT + 16;

constexpr int SMEM_BYTES = O_FEND * 4 + I_END * 4;   // ~112.4 KB -> 2 CTAs/SM

__device__ __forceinline__ float sigm(float z) {
    return 1.0f / (1.0f + __expf(-z));
}

__device__ __forceinline__ int off_cf(int v) {
    if (v <= 0)  return 0;
    if (v <= 10) return 3 * v - 1;
    if (v <= 32) return 2 * v + 9;
    if (v <= 42) return 3 * v - 23;
    if (v <= 63) return 2 * v + 19;
    return MAXE;
}

// copy peer CTA's own-half (32 rows x 64) of an arena into our arena.
__device__ __forceinline__ void xchg_half(float* loc, const float* peer,
                                          int prank, int t) {
    ((float4*)loc)[prank * 512 + t] =
        ((const float4*)peer)[prank * 512 + t];
}

// ---------------- one GNN layer (compile-time F / first) --------------------
// Work split across the 2-CTA cluster: node GEMMs / msg / LN for own 32
// nodes, edge update for own 73 CSR rows. XJ and XV halves exchanged via
// DSMEM (peer smem) around cluster.sync().
template<int F, bool FIRST>
__device__ __forceinline__ void run_layer(
    const float* __restrict__ Ws, const float* __restrict__ Wi,
    const float* __restrict__ Wj, const float* __restrict__ U,
    const float* __restrict__ Vw,
    float* sS, float* sX, float* sB0, float* sB1, float* sW,
    const float* sEmb, const float* sDi,
    const int* sEv, const int* sEw, const int* sEfl, const int* sOff,
    float* psmf, int rank, int t, int lane, int wid)
{
    cg::cluster_group cluster = cg::this_cluster();
    const int prank = rank ^ 1;
    const int vbase = rank * HNOD;
    const int ebase = rank * HEDG;

    // ---- stage Wi -> sW (plain), Wj -> sB1 ---------------------------------
    #pragma unroll
    for (int i = t; i < F * HID; i += NT) {
        sW[i]  = Wi[i];
        sB1[i] = Wj[i];
    }
    __syncthreads();

    // ---- XI -> sB0 (own rows), XJ -> regs ----------------------------------
    int k = t & 63, vg = t >> 6;
    int rbase = vbase + vg * 4;
    float aJ[4];
    {
        float aI[4];
        #pragma unroll
        for (int j = 0; j < 4; j++) { aI[j] = 0.f; aJ[j] = 0.f; }
        #pragma unroll 4
        for (int h = 0; h < F; h += 4) {
            float wi0 = sW[(h    ) * HID + k], wj0 = sB1[(h    ) * HID + k];
            float wi1 = sW[(h + 1) * HID + k], wj1 = sB1[(h + 1) * HID + k];
            float wi2 = sW[(h + 2) * HID + k], wj2 = sB1[(h + 2) * HID + k];
            float wi3 = sW[(h + 3) * HID + k], wj3 = sB1[(h + 3) * HID + k];
            #pragma unroll
            for (int j = 0; j < 4; j++) {
                float4 xv = *(const float4*)&sX[(rbase + j) * HID + h];
                aI[j] = fmaf(xv.x, wi0, aI[j]);
                aI[j] = fmaf(xv.y, wi1, aI[j]);
                aI[j] = fmaf(xv.z, wi2, aI[j]);
                aI[j] = fmaf(xv.w, wi3, aI[j]);
                aJ[j] = fmaf(xv.x, wj0, aJ[j]);
                aJ[j] = fmaf(xv.y, wj1, aJ[j]);
                aJ[j] = fmaf(xv.z, wj2, aJ[j]);
                aJ[j] = fmaf(xv.w, wj3, aJ[j]);
            }
        }
        #pragma unroll
        for (int j = 0; j < 4; j++)
            sB0[(rbase + j) * HID + k] = aI[j];
    }
    __syncthreads();            // weight reads complete

    // ---- write XJ (own rows); stage Ws transposed into sW -------------------
    #pragma unroll
    for (int j = 0; j < 4; j++)
        sB1[(rbase + j) * HID + k] = aJ[j];
    #pragma unroll
    for (int i = t; i < F * HID; i += NT) {
        int kk = i & 63, h = i >> 6;
        sW[kk * WPAD + h] = Ws[h * HID + kk];
    }
    __syncthreads();

    // ---- exchange XJ halves (edge phase needs full XJ) ----------------------
    cluster.sync();
    xchg_half(sB1, psmf + O_B1, prank, t);
    __syncthreads();

    // ---- edge update (own 73 edges): relu(LN(s@Ws + XI[v] + XJ[w])) ---------
    {
        const float* wrow0 = sW + lane * WPAD;
        const float* wrow1 = sW + (lane + 32) * WPAD;
        if (FIRST) {
            float c00 = 0.f, c01 = 0.f, c10 = 0.f, c11 = 0.f;
            #pragma unroll
            for (int h = 0; h < FIN; h += 4) {
                float4 w0 = *(const float4*)&wrow0[h];
                float4 w1 = *(const float4*)&wrow1[h];
                float4 s0 = *(const float4*)&sEmb[h];
                float4 s1 = *(const float4*)&sEmb[FIN + h];
                c00 = fmaf(s0.x, w0.x, c00); c00 = fmaf(s0.y, w0.y, c00);
                c00 = fmaf(s0.z, w0.z, c00); c00 = fmaf(s0.w, w0.w, c00);
                c01 = fmaf(s0.x, w1.x, c01); c01 = fmaf(s0.y, w1.y, c01);
                c01 = fmaf(s0.z, w1.z, c01); c01 = fmaf(s0.w, w1.w, c01);
                c10 = fmaf(s1.x, w0.x, c10); c10 = fmaf(s1.y, w0.y, c10);
                c10 = fmaf(s1.z, w0.z, c10); c10 = fmaf(s1.w, w0.w, c10);
                c11 = fmaf(s1.x, w1.x, c11); c11 = fmaf(s1.y, w1.y, c11);
                c11 = fmaf(s1.z, w1.z, c11); c11 = fmaf(s1.w, w1.w, c11);
            }
            #pragma unroll
            for (int q = 0; q < 5; q++) {
                int e = ebase + wid + q * NWARP;       // warp-uniform
                if (e < ebase + HEDG) {
                    int v = sEv[e], w = sEw[e], fl = sEfl[e];
                    float acc0 = fl ? c10 : c00;
                    float acc1 = fl ? c11 : c01;
                    float e0 = acc0 + sB0[v * HID + lane]      + sB1[w * HID + lane];
                    float e1 = acc1 + sB0[v * HID + lane + 32] + sB1[w * HID + lane + 32];
                    float s1 = e0 + e1, s2 = e0 * e0 + e1 * e1;
                    #pragma unroll
                    for (int o = 16; o > 0; o >>= 1) {
                        s1 += __shfl_xor_sync(0xffffffffu, s1, o);
                        s2 += __shfl_xor_sync(0xffffffffu, s2, o);
                    }
                    float mean = s1 * (1.0f / 64.0f);
                    float var  = s2 * (1.0f / 64.0f) - mean * mean;
                    float rs   = rsqrtf(var + 1e-5f);
                    sS[e * HID + lane]      = fmaxf((e0 - mean) * rs, 0.0f);
                    sS[e * HID + lane + 32] = fmaxf((e1 - mean) * rs, 0.0f);
                }
            }
        } else {
            float acc0[5], acc1[5];
            int   soff[5];
            #pragma unroll
            for (int q = 0; q < 5; q++) {
                acc0[q] = 0.f; acc1[q] = 0.f;
                int e  = ebase + wid + q * NWARP;
                soff[q] = ((e < ebase + HEDG) ? e : ebase) * HID;
            }
            #pragma unroll 2
            for (int h = 0; h < F; h += 4) {
                float4 w0 = *(const float4*)&wrow0[h];
                float4 w1 = *(const float4*)&wrow1[h];
                #pragma unroll
                for (int q = 0; q < 5; q++) {
                    float4 sv = *(const float4*)&sS[soff[q] + h];
                    acc0[q] = fmaf(sv.x, w0.x, acc0[q]);
                    acc0[q] = fmaf(sv.y, w0.y, acc0[q]);
                    acc0[q] = fmaf(sv.z, w0.z, acc0[q]);
                    acc0[q] = fmaf(sv.w, w0.w, acc0[q]);
                    acc1[q] = fmaf(sv.x, w1.x, acc1[q]);
                    acc1[q] = fmaf(sv.y, w1.y, acc1[q]);
                    acc1[q] = fmaf(sv.z, w1.z, acc1[q]);
                    acc1[q] = fmaf(sv.w, w1.w, acc1[q]);
                }
            }
            #pragma unroll
            for (int q = 0; q < 5; q++) {
                int e = ebase + wid + q * NWARP;       // warp-uniform
                if (e < ebase + HEDG) {
                    int v = sEv[e], w = sEw[e];
                    float e0 = acc0[q] + sB0[v * HID + lane]      + sB1[w * HID + lane];
                    float e1 = acc1[q] + sB0[v * HID + lane + 32] + sB1[w * HID + lane + 32];
                    float s1 = e0 + e1, s2 = e0 * e0 + e1 * e1;
                    #pragma unroll
                    for (int o = 16; o > 0; o >>= 1) {
                        s1 += __shfl_xor_sync(0xffffffffu, s1, o);
                        s2 += __shfl_xor_sync(0xffffffffu, s2, o);
                    }
                    float mean = s1 * (1.0f / 64.0f);
                    float var  = s2 * (1.0f / 64.0f) - mean * mean;
                    float rs   = rsqrtf(var + 1e-5f);
                    float r0 = fmaxf((e0 - mean) * rs, 0.0f) + sS[e * HID + lane];
                    float r1 = fmaxf((e1 - mean) * rs, 0.0f) + sS[e * HID + lane + 32];
                    sS[e * HID + lane]      = r0;
                    sS[e * HID + lane + 32] = r1;
                }
            }
        }
    }
    __syncthreads();

    // ---- stage Vw -> sW (plain), U -> sB1 (XJ dead) --------------------------
    #pragma unroll
    for (int i = t; i < F * HID; i += NT) {
        sW[i]  = Vw[i];
        sB1[i] = U[i];
    }
    __syncthreads();

    // ---- XV -> sB0 (own rows), XU -> regs ------------------------------------
    float aU[4];
    {
        float aV[4];
        #pragma unroll
        for (int j = 0; j < 4; j++) { aV[j] = 0.f; aU[j] = 0.f; }
        #pragma unroll 4
        for (int h = 0; h < F; h += 4) {
            float wv0 = sW[(h    ) * HID + k], wu0 = sB1[(h    ) * HID + k];
            float wv1 = sW[(h + 1) * HID + k], wu1 = sB1[(h + 1) * HID + k];
            float wv2 = sW[(h + 2) * HID + k], wu2 = sB1[(h + 2) * HID + k];
            float wv3 = sW[(h + 3) * HID + k], wu3 = sB1[(h + 3) * HID + k];
            #pragma unroll
            for (int j = 0; j < 4; j++) {
                float4 xv = *(const float4*)&sX[(rbase + j) * HID + h];
                aV[j] = fmaf(xv.x, wv0, aV[j]);
                aV[j] = fmaf(xv.y, wv1, aV[j]);
                aV[j] = fmaf(xv.z, wv2, aV[j]);
                aV[j] = fmaf(xv.w, wv3, aV[j]);
                aU[j] = fmaf(xv.x, wu0, aU[j]);
                aU[j] = fmaf(xv.y, wu1, aU[j]);
                aU[j] = fmaf(xv.z, wu2, aU[j]);
                aU[j] = fmaf(xv.w, wu3, aU[j]);
            }
        }
        #pragma unroll
        for (int j = 0; j < 4; j++)
            sB0[(rbase + j) * HID + k] = aV[j];
    }
    __syncthreads();            // weight reads complete

    #pragma unroll
    for (int j = 0; j < 4; j++)
        sB1[(rbase + j) * HID + k] = aU[j];
    __syncthreads();

    // ---- exchange XV halves (msg needs full XV) ------------------------------
    cluster.sync();
    xchg_half(sB0, psmf + O_B0, prank, t);
    __syncthreads();

    // ---- fused msg + node LN: warp-per-node, own 32 nodes --------------------
    #pragma unroll
    for (int it = 0; it < 2; it++) {
        int v = vbase + wid + it * NWARP;
        float a0 = 0.f, a1 = 0.f;
        int eb = sOff[v], ee = sOff[v + 1];
        for (int e = eb; e < ee; e++) {
            int w = sEw[e];
            a0 = fmaf(sigm(sS[e * HID + lane]),      sB0[w * HID + lane],      a0);
            a1 = fmaf(sigm(sS[e * HID + lane + 32]), sB0[w * HID + lane + 32], a1);
        }
        float di = sDi[v];
        float z0 = fmaf(a0, di, sB1[v * HID + lane]);
        float z1 = fmaf(a1, di, sB1[v * HID + lane + 32]);
        float s1 = z0 + z1, s2 = z0 * z0 + z1 * z1;
        #pragma unroll
        for (int o = 16; o > 0; o >>= 1) {
            s1 += __shfl_xor_sync(0xffffffffu, s1, o);
            s2 += __shfl_xor_sync(0xffffffffu, s2, o);
        }
        float mean = s1 * (1.0f / 64.0f);
        float var  = s2 * (1.0f / 64.0f) - mean * mean;
        float rs   = rsqrtf(var + 1e-5f);
        float r0 = fmaxf((z0 - mean) * rs, 0.0f);
        float r1 = fmaxf((z1 - mean) * rs, 0.0f);
        if (!FIRST) { r0 += sX[v * HID + lane]; r1 += sX[v * HID + lane + 32]; }
        sX[v * HID + lane]      = r0;
        sX[v * HID + lane + 32] = r1;
    }
    __syncthreads();
}

__global__ __launch_bounds__(NT, 2) __cluster_dims__(2, 1, 1)
void gnn_kernel(const float* __restrict__ x_in,
                const float* __restrict__ embed_s,
                const float* __restrict__ p0_Ws, const float* __restrict__ p0_Wi,
                const float* __restrict__ p0_Wj, const float* __restrict__ p0_U,
                const float* __restrict__ p0_V,
                const float* __restrict__ pl_Ws, const float* __restrict__ pl_Wi,
                const float* __restrict__ pl_Wj, const float* __restrict__ pl_U,
                const float* __restrict__ pl_V,
                const float* __restrict__ sW1,  const float* __restrict__ sW2,
                const float* __restrict__ cW1,  const float* __restrict__ cW2,
                const float* __restrict__ Dinv,
                float* __restrict__ out) {
    extern __shared__ float smf[];
    float* sS   = smf + O_S;
    float* sX   = smf + O_X;
    float* sB0  = smf + O_B0;
    float* sB1  = smf + O_B1;
    float* sW   = smf + O_W;
    float* sXg  = smf + O_XG;
    float* sEmb = smf + O_EMB;
    float* sSw  = smf + O_SW;
    float* sG   = smf + O_G;
    float* sOutS= smf + O_OUTS;
    float* sOutC= smf + O_OUTC;
    float* sVp  = smf + O_VP;
    float* sVc  = smf + O_VC;
    float* sDi  = smf + O_DI;
    int*   smi  = (int*)(smf + O_FEND);
    int* sEv = smi + I_EV;  int* sEw = smi + I_EW;  int* sEfl = smi + I_EFL;
    int* sOff= smi + I_OFF; int* sAi = smi + I_AI;  int* sAj  = smi + I_AJ;
    int* sSi = smi + I_SI;  int* sSj = smi + I_SJ;  int* sSlot= smi + I_SLOT;
    float* sHid = smf + O_B0;   // 63*192 = 12096 <= 12544 contiguous (B0,B1,W)

    cg::cluster_group cluster = cg::this_cluster();
    const int rank  = (int)cluster.block_rank();
    float*    psmf  = cluster.map_shared_rank(smf, rank ^ 1);

    const int t    = threadIdx.x;
    const int b    = blockIdx.x >> 1;
    const int lane = t & 31;
    const int wid  = t >> 5;

    // ---- per-batch x (float4) + closed-form topology (both ranks, full) -----
    {
        const float4* xi4 = (const float4*)(x_in + b * VN * FIN);
        int v = t >> 3, h = (t & 7) * 4;
        *(float4*)&sX[v * HID + h] = xi4[t];
    }
    if (t < VN)  sEmb[t] = embed_s[t];
    if (t < MAXE) {
        int e = t, v, base;
        if (e < 2)        { v = 0;                base = 0; }
        else if (e < 29)  { v = 1 + (e - 2) / 3;  base = 3 * v - 1; }
        else if (e < 73)  { v = 10 + (e - 29) / 2; base = 2 * v + 9; }
        else if (e < 103) { v = 32 + (e - 73) / 3; base = 3 * v - 23; }
        else if (e < 145) { v = 42 + (e - 103) / 2; base = 2 * v + 19; }
        else              { v = 63;               base = 145; }
        int idx = e - base;
        int n0 = (v >= 32 && v <= 41) ? 1 : 0;
        int n1 = (v >= 1) ? 1 : 0;
        int n2 = (v <= 62) ? 1 : 0;
        int w, fl;
        if (idx < n0)                { w = v - 32; fl = 1; }
        else if (idx < n0 + n1)      { w = v - 1;  fl = 0; }
        else if (idx < n0 + n1 + n2) { w = v + 1;  fl = 0; }
        else                         { w = v + 32; fl = 1; }
        sEv[e] = v; sEw[e] = w; sEfl[e] = fl;
    }
    if (t <= VN) {
        int o0 = off_cf(t);
        sOff[t] = o0;
        if (t < VN) sDi[t] = 1.0f / (float)(off_cf(t + 1) - o0);
    }
    if (t < ECNT) { sAi[t] = t; sAj[t] = t + 1; }
    if (t < NSW)  { sSi[t] = t; sSj[t] = t + 32;
                    sSlot[t] = (t == 0) ? 1 : (3 * t + 1); }
    __syncthreads();

    // ---- 3 GNN layers (cluster-split) ---------------------------------------
    run_layer<FIN, true>(p0_Ws, p0_Wi, p0_Wj, p0_U, p0_V,
                         sS, sX, sB0, sB1, sW, sEmb, sDi,
                         sEv, sEw, sEfl, sOff, psmf, rank, t, lane, wid);
    run_layer<HID, false>(pl_Ws, pl_Wi, pl_Wj, pl_U, pl_V,
                          sS, sX, sB0, sB1, sW, sEmb, sDi,
                          sEv, sEw, sEfl, sOff, psmf, rank, t, lane, wid);
    run_layer<HID, false>(pl_Ws + HID * HID, pl_Wi + HID * HID,
                          pl_Wj + HID * HID, pl_U + HID * HID, pl_V + HID * HID,
                          sS, sX, sB0, sB1, sW, sEmb, sDi,
                          sEv, sEw, sEfl, sOff, psmf, rank, t, lane, wid);

    // ---- exchange sX halves once before heads --------------------------------
    cluster.sync();
    xchg_half(sX, psmf + O_X, rank ^ 1, t);
    __syncthreads();

    // ---- heads (split: rank0 smlp + cmlp rows 0-31, rank1 cmlp rows 32-62) --
    if (rank == 0) {
        for (int i = t; i < NSW * HID; i += NT) {
            int r = i >> 6, kk = i & 63;
            sSw[i] = sS[sSlot[r] * HID + kk];   // all switch slots < 73 (rank0)
        }
    }
    if (t < HID) {
        float a = 0.f;
        #pragma unroll 4
        for (int v = 0; v < VN; v++) a += sX[v * HID + t];
        sXg[t] = a;
    }
    __syncthreads();

    // smlp hidden (rank 0 only; 10 x 256 -> sS scratch)
    if (rank == 0) {
        int k = t & 255, rg = t >> 8;
        int idxI[5], idxJ[5];
        #pragma unroll
        for (int q = 0; q < 5; q++) { idxI[q] = sSi[rg * 5 + q] * HID; idxJ[q] = sSj[rg * 5 + q] * HID; }
        float acc[5];
        #pragma unroll
        for (int q = 0; q < 5; q++) acc[q] = 0.f;
        #pragma unroll 2
        for (int i = 0; i < 64; i += 4) {
            float w0 = sW1[(i    ) * 256 + k], w1 = sW1[(i + 1) * 256 + k];
            float w2 = sW1[(i + 2) * 256 + k], w3 = sW1[(i + 3) * 256 + k];
            #pragma unroll
            for (int q = 0; q < 5; q++) {
                float4 sv = *(const float4*)&sSw[(rg * 5 + q) * HID + i];
                acc[q] = fmaf(sv.x, w0, acc[q]);
                acc[q] = fmaf(sv.y, w1, acc[q]);
                acc[q] = fmaf(sv.z, w2, acc[q]);
                acc[q] = fmaf(sv.w, w3, acc[q]);
            }
        }
        #pragma unroll 2
        for (int i = 0; i < 64; i += 4) {
            float w0 = sW1[(64 + i    ) * 256 + k], w1 = sW1[(64 + i + 1) * 256 + k];
            float w2 = sW1[(64 + i + 2) * 256 + k], w3 = sW1[(64 + i + 3) * 256 + k];
            #pragma unroll
            for (int q = 0; q < 5; q++) {
                float4 xv = *(const float4*)&sX[idxI[q] + i];
                acc[q] = fmaf(xv.x, w0, acc[q]);
                acc[q] = fmaf(xv.y, w1, acc[q]);
                acc[q] = fmaf(xv.z, w2, acc[q]);
                acc[q] = fmaf(xv.w, w3, acc[q]);
            }
        }
        #pragma unroll 2
        for (int i = 0; i < 64; i += 4) {
            float w0 = sW1[(128 + i    ) * 256 + k], w1 = sW1[(128 + i + 1) * 256 + k];
            float w2 = sW1[(128 + i + 2) * 256 + k], w3 = sW1[(128 + i + 3) * 256 + k];
            #pragma unroll
            for (int q = 0; q < 5; q++) {
                float4 xv = *(const float4*)&sX[idxJ[q] + i];
                acc[q] = fmaf(xv.x, w0, acc[q]);
                acc[q] = fmaf(xv.y, w1, acc[q]);
                acc[q] = fmaf(xv.z, w2, acc[q]);
                acc[q] = fmaf(xv.w, w3, acc[q]);
            }
        }
        #pragma unroll 2
        for (int i = 0; i < 64; i += 4) {
            float w0 = sW1[(192 + i    ) * 256 + k], w1 = sW1[(192 + i + 1) * 256 + k];
            float w2 = sW1[(192 + i + 2) * 256 + k], w3 = sW1[(192 + i + 3) * 256 + k];
            float4 g = *(const float4*)&sXg[i];
            #pragma unroll
            for (int q = 0; q < 5; q++) {
                acc[q] = fmaf(g.x, w0, acc[q]);
                acc[q] = fmaf(g.y, w1, acc[q]);
                acc[q] = fmaf(g.z, w2, acc[q]);
                acc[q] = fmaf(g.w, w3, acc[q]);
            }
        }
        #pragma unroll
        for (int q = 0; q < 5; q++)
            sS[(rg * 5 + q) * 256 + k] = fmaxf(acc[q], 0.0f);
    }
    __syncthreads();

    // smlp out (rank0 warps 8-15) + cmlp graph-term sG (both ranks)
    if (rank == 0 && wid >= 8) {
        int w8 = wid - 8;
        #pragma unroll
        for (int q = 0; q < 5; q++) {
            int o = w8 * 5 + q;
            int r = o >> 2, j = o & 3;
            float a = 0.f;
            #pragma unroll
            for (int kk = 0; kk < 256; kk += 32)
                a = fmaf(sS[r * 256 + kk + lane], sW2[(kk + lane) * 4 + j], a);
            #pragma unroll
            for (int off = 16; off > 0; off >>= 1)
                a += __shfl_xor_sync(0xffffffffu, a, off);
            if (lane == 0) sOutS[o] = sigm(a);
        }
    } else if (t >= 64 && t < 256) {
        int k = t - 64;
        float a = 0.f;
        #pragma unroll 4
        for (int i = 0; i < 64; i++)
            a = fmaf(sXg[i], cW1[(128 + i) * 192 + k], a);
        sG[k] = a;
    }
    __syncthreads();

    // cmlp hidden: own 32 rows (rank*32 ..), 2 passes of 2x8 rows
    if (t < 384) {
        int k = t % 192, half = t / 192;
        #pragma unroll 1
        for (int p = 0; p < 2; p++) {
            int r0 = rank * HNOD + p * 16 + half * 8;
            float acc[8];
            int bA[8], bB[8];
            #pragma unroll
            for (int q = 0; q < 8; q++) {
                int r = r0 + q;
                int rr = (r < ECNT) ? r : 0;
                acc[q] = 0.f;
                bA[q] = sAi[rr] * HID;
                bB[q] = sAj[rr] * HID;
            }
            #pragma unroll 2
            for (int i = 0; i < 64; i += 4) {
                float wa0 = cW1[(i    ) * 192 + k], wa1 = cW1[(i + 1) * 192 + k];
                float wa2 = cW1[(i + 2) * 192 + k], wa3 = cW1[(i + 3) * 192 + k];
                float wb0 = cW1[(64 + i    ) * 192 + k], wb1 = cW1[(64 + i + 1) * 192 + k];
                float wb2 = cW1[(64 + i + 2) * 192 + k], wb3 = cW1[(64 + i + 3) * 192 + k];
                #pragma unroll
                for (int q = 0; q < 8; q++) {
                    float4 xa = *(const float4*)&sX[bA[q] + i];
                    float4 xb = *(const float4*)&sX[bB[q] + i];
                    acc[q] = fmaf(xa.x, wa0, acc[q]);
                    acc[q] = fmaf(xa.y, wa1, acc[q]);
                    acc[q] = fmaf(xa.z, wa2, acc[q]);
                    acc[q] = fmaf(xa.w, wa3, acc[q]);
                    acc[q] = fmaf(xb.x, wb0, acc[q]);
                    acc[q] = fmaf(xb.y, wb1, acc[q]);
                    acc[q] = fmaf(xb.z, wb2, acc[q]);
                    acc[q] = fmaf(xb.w, wb3, acc[q]);
                }
            }
            #pragma unroll
            for (int q = 0; q < 8; q++) {
                int r = r0 + q;
                if (r < ECNT)
                    sHid[r * 192 + k] = fmaxf(acc[q] + sG[k], 0.0f);
            }
        }
    }
    __syncthreads();

    // cmlp out: own rows -> own o-range (rank0: o<96, rank1: 96..188)
    {
        int obase = rank * 96;
        int oend  = rank ? ECNT * 3 : 96;
        for (int o = obase + wid; o < oend; o += NWARP) {
            int r = o / 3, j = o - r * 3;
            float a = 0.f;
            #pragma unroll
            for (int kk = 0; kk < 192; kk += 32)
                a = fmaf(sHid[r * 192 + kk + lane], cW2[(kk + lane) * 3 + j], a);
            #pragma unroll
            for (int off = 16; off > 0; off >>= 1)
                a += __shfl_xor_sync(0xffffffffu, a, off);
            if (lane == 0) sOutC[o] = sigm(a);
        }
    }
    __syncthreads();

    // merge head outputs on rank 0; rank 1 just keeps smem alive
    cluster.sync();
    if (rank == 0) {
        const float* pOutC = psmf + O_OUTC;
        if (t < ECNT * 3 - 96) sOutC[96 + t] = pOutC[96 + t];
        __syncthreads();

        // per-edge parent/child voltages; zero node accumulator (reuse sXg)
        if (t < MN) {
            float o1, o2;
            if (t < ECNT) { o1 = sOutC[t * 3 + 1]; o2 = sOutC[t * 3 + 2]; }
            else          { o1 = sOutS[(t - ECNT) * 4 + 2]; o2 = sOutS[(t - ECNT) * 4 + 3]; }
            sVp[t] = 0.9f + 0.2f * o1;
            sVc[t] = 0.9f + 0.2f * o2;
        }
        if (t < VN) sXg[t] = 0.f;
        __syncthreads();

        if (t < MN) {
            int p = (t < ECNT) ? sAi[t] : sSi[t - ECNT];
            int c = (t < ECNT) ? sAj[t] : sSj[t - ECNT];
            atomicAdd(&sXg[p], sVp[t]);
            atomicAdd(&sXg[c], sVc[t]);
        }
        __syncthreads();

        // ---- output assembly: [p_flow(73) | v(64) | graph_topo(73)] ---------
        float* ob = out + b * OUTW;
        for (int i = t; i < OUTW; i += NT) {
            float val;
            if (i < ECNT) {
                val = sOutC[i * 3] - 0.5f;
            } else if (i < MN) {
                val = sOutS[(i - ECNT) * 4 + 1] - 0.5f;
            } else if (i < MN + VN) {
                int n = i - MN;
                val = (n == 0) ? 1.0f : Dinv[n * VN + n] * sXg[n];
            } else if (i < MN + VN + ECNT) {
                val = 1.0f;
            } else {
                val = sOutS[(i - (MN + VN + ECNT)) * 4];
            }
            ob[i] = val;
        }
    }
    cluster.sync();   // rank1 smem must stay mapped until rank0 is done
}

extern "C" void kernel_launch(void* const* d_in, const int* in_sizes, int n_in,
                              void* d_out, int out_size) {
    const float* x       = (const float*)d_in[0];
    const float* embed_s = (const float*)d_in[3];
    const float* p0_Ws   = (const float*)d_in[4];
    const float* p0_Wi   = (const float*)d_in[5];
    const float* p0_Wj   = (const float*)d_in[6];
    const float* p0_U    = (const float*)d_in[7];
    const float* p0_V    = (const float*)d_in[8];
    const float* pl_Ws   = (const float*)d_in[9];
    const float* pl_Wi   = (const float*)d_in[10];
    const float* pl_Wj   = (const float*)d_in[11];
    const float* pl_U    = (const float*)d_in[12];
    const float* pl_V    = (const float*)d_in[13];
    const float* smlp_W1 = (const float*)d_in[14];
    const float* smlp_W2 = (const float*)d_in[15];
    const float* cmlp_W1 = (const float*)d_in[16];
    const float* cmlp_W2 = (const float*)d_in[17];
    const float* Dinv    = (const float*)d_in[18];
    float*       out     = (float*)d_out;

    cudaFuncSetAttribute(gnn_kernel, cudaFuncAttributeMaxDynamicSharedMemorySize,
                         SMEM_BYTES);

    gnn_kernel<<<2 * BN, NT, SMEM_BYTES>>>(x, embed_s,
                                           p0_Ws, p0_Wi, p0_Wj, p0_U, p0_V,
                                           pl_Ws, pl_Wi, pl_Wj, pl_U, pl_V,
                                           smlp_W1, smlp_W2, cmlp_W1, cmlp_W2,
                                           Dinv, out);
}